// round 7
// baseline (speedup 1.0000x reference)
#include <cuda_runtime.h>
#include <cuda_fp16.h>
#include <cstdint>

#define NUM_USERS 100000
#define NUM_ITEMS 50000
#define N_NODES   150000
#define DIM       64
#define NNZ_MAX   4800000
#define FULL      0xffffffffu

// ---- static device scratch (referenced ONLY from device code) ----
__device__ float   g_acc  [(size_t)N_NODES * DIM];      // fp32: ego + c1 + c2
__device__ __half2 g_ego_h[(size_t)N_NODES * DIM / 2];
__device__ __half2 g_c1_h [(size_t)N_NODES * DIM / 2];
__device__ __half2 g_c2_h [(size_t)N_NODES * DIM / 2];
__device__ int   g_cnt   [N_NODES];
__device__ int   g_start [N_NODES];
__device__ int   g_cursor[N_NODES];
__device__ int2  g_edges [NNZ_MAX];
__device__ int   g_partials[256];

// fused: fp16 ego copy + zero counters
__global__ void k_init_hist(const float* __restrict__ ue, const float* __restrict__ ie) {
    int i = blockIdx.x * blockDim.x + threadIdx.x;
    if (i < N_NODES * DIM / 4) {
        const int u4 = NUM_USERS * DIM / 4;
        float4 v = (i < u4) ? ((const float4*)ue)[i] : ((const float4*)ie)[i - u4];
        g_ego_h[i * 2]     = __float22half2_rn(make_float2(v.x, v.y));
        g_ego_h[i * 2 + 1] = __float22half2_rn(make_float2(v.z, v.w));
    }
    if (i < N_NODES / 4) ((int4*)g_cnt)[i] = make_int4(0, 0, 0, 0);
}

__global__ void k_hist(const int* __restrict__ rows, int nnz) {
    int e = blockIdx.x * blockDim.x + threadIdx.x;
    if (e < nnz) atomicAdd(&g_cnt[__ldg(rows + e)], 1);
}

__global__ void k_scan1(int n) {
    __shared__ int sh[1024];
    int i = blockIdx.x * 1024 + threadIdx.x;
    sh[threadIdx.x] = (i < n) ? g_cnt[i] : 0;
    __syncthreads();
    #pragma unroll
    for (int off = 1; off < 1024; off <<= 1) {
        int t = (threadIdx.x >= off) ? sh[threadIdx.x - off] : 0;
        __syncthreads();
        sh[threadIdx.x] += t;
        __syncthreads();
    }
    if (i < n) g_start[i] = sh[threadIdx.x];
    if (threadIdx.x == 1023) g_partials[blockIdx.x] = sh[1023];
}

// fused scan2+scan3: each block reduces partials[0..blockIdx.x) itself
__global__ void k_scan23(int n, int nb) {
    __shared__ int sh[256];
    int t = threadIdx.x;
    if (t < 256) {
        sh[t] = (t < blockIdx.x && t < nb) ? g_partials[t] : 0;
    }
    __syncthreads();
    #pragma unroll
    for (int off = 128; off; off >>= 1) {
        if (t < off) sh[t] += sh[t + off];
        __syncthreads();
    }
    int offset = sh[0];
    int i = blockIdx.x * 1024 + t;
    if (i < n) {
        int s = g_start[i] - g_cnt[i] + offset;
        g_start[i]  = s;
        g_cursor[i] = s;
    }
}

__global__ void k_scatter(const int* __restrict__ rows, const int* __restrict__ cols,
                          const float* __restrict__ vals, int nnz) {
    int e = blockIdx.x * blockDim.x + threadIdx.x;
    if (e >= nnz) return;
    int r   = __ldg(rows + e);
    int pos = atomicAdd(&g_cursor[r], 1);
    g_edges[pos] = make_int2(__ldg(cols + e), __float_as_int(__ldg(vals + e)));
}

// ---- paired-edge gather: one warp per row, lanes 0-15 = even edges,
// lanes 16-31 = odd edges; each half-warp spans the 128B row at 8B/lane.
// One LDG.64 fetches x for TWO edges; one SHFL broadcasts per edge.
// mode 0: c1 = A @ ego_h ; acc = ego(fp32) + c1
// mode 1: c2 = A @ c1_h  ; acc += c2
__global__ void k_gather(int mode, const float* __restrict__ ue,
                         const float* __restrict__ ie) {
    int w = (blockIdx.x * blockDim.x + threadIdx.x) >> 5;
    if (w >= N_NODES) return;
    int lane = threadIdx.x & 31;
    int h    = lane >> 4;       // which edge of the pair
    int sub  = lane & 15;       // position within the row (dims 4*sub..4*sub+3)

    const __half2* __restrict__ x = mode ? g_c1_h : g_ego_h;
    int base = __ldg(&g_start[w]);
    int len  = __ldg(&g_cnt[w]);
    const int2* __restrict__ ep = g_edges + base;

    float4 s = make_float4(0.f, 0.f, 0.f, 0.f);

    for (int chunk = 0; chunk < len; chunk += 32) {
        int m = min(32, len - chunk);
        int2 e = make_int2(0, 0);                  // col 0, val +0.0f (safe no-op)
        if (lane < m) e = __ldg(ep + chunk + lane);
        int pairs = (m + 1) >> 1;
        #pragma unroll 8
        for (int k = 0; k < pairs; k++) {
            int   src = 2 * k + h;
            int   col = __shfl_sync(FULL, e.x, src);
            float v   = __int_as_float(__shfl_sync(FULL, e.y, src));
            uint2 raw = __ldg((const uint2*)(x + (size_t)col * 32 + 2 * sub));
            __half2 h0 = *reinterpret_cast<__half2*>(&raw.x);
            __half2 h1 = *reinterpret_cast<__half2*>(&raw.y);
            float2 f0 = __half22float2(h0);
            float2 f1 = __half22float2(h1);
            s.x = fmaf(v, f0.x, s.x);
            s.y = fmaf(v, f0.y, s.y);
            s.z = fmaf(v, f1.x, s.z);
            s.w = fmaf(v, f1.y, s.w);
        }
    }

    // fold odd-edge half into even-edge half
    s.x += __shfl_xor_sync(FULL, s.x, 16);
    s.y += __shfl_xor_sync(FULL, s.y, 16);
    s.z += __shfl_xor_sync(FULL, s.z, 16);
    s.w += __shfl_xor_sync(FULL, s.w, 16);

    if (h == 0) {
        // fp16 layer output: half2 slots 2*sub, 2*sub+1 (8B store)
        uint2 packed;
        __half2 o0 = __float22half2_rn(make_float2(s.x, s.y));
        __half2 o1 = __float22half2_rn(make_float2(s.z, s.w));
        packed.x = *reinterpret_cast<unsigned int*>(&o0);
        packed.y = *reinterpret_cast<unsigned int*>(&o1);
        size_t ho = (size_t)w * 32 + 2 * sub;
        if (mode == 0) *reinterpret_cast<uint2*>(&g_c1_h[ho]) = packed;
        else           *reinterpret_cast<uint2*>(&g_c2_h[ho]) = packed;

        // fp32 accumulator
        float4 a;
        if (mode == 0) {
            const float4* __restrict__ src4 = (w < NUM_USERS)
                ? (const float4*)(ue + (size_t)w * DIM)
                : (const float4*)(ie + (size_t)(w - NUM_USERS) * DIM);
            a = __ldg(src4 + sub);
        } else {
            a = ((float4*)g_acc)[(size_t)w * 16 + sub];
        }
        a.x += s.x; a.y += s.y; a.z += s.z; a.w += s.w;
        ((float4*)g_acc)[(size_t)w * 16 + sub] = a;
    }
}

// classic 32-lane row gather (half2 per lane) — used for lazy layer 3 in dot
__device__ __forceinline__ float2 row_gather(const __half2* __restrict__ x,
                                             int base, int len, int lane) {
    const int2* __restrict__ ep = g_edges + base;
    float2 s = make_float2(0.f, 0.f);
    for (int chunk = 0; chunk < len; chunk += 32) {
        int m = min(32, len - chunk);
        int2 e = make_int2(0, 0);
        if (lane < m) e = __ldg(ep + chunk + lane);
        #pragma unroll 8
        for (int k = 0; k < m; k++) {
            int   col = __shfl_sync(FULL, e.x, k);
            float v   = __int_as_float(__shfl_sync(FULL, e.y, k));
            float2 xv = __half22float2(__ldg(&x[(size_t)col * 32 + lane]));
            s.x = fmaf(v, xv.x, s.x);
            s.y = fmaf(v, xv.y, s.y);
        }
    }
    return s;
}

// lazy layer 3 + dot: one warp per (user,item) pair.
__global__ void k_dot(const int* __restrict__ users, const int* __restrict__ items,
                      float* __restrict__ out, int batch) {
    int w    = (blockIdx.x * blockDim.x + threadIdx.x) >> 5;
    int lane = threadIdx.x & 31;
    if (w >= batch) return;

    int r0 = __ldg(users + w);
    int r1 = NUM_USERS + __ldg(items + w);

    float2 va, vb;
    {
        float2 s = row_gather(g_c2_h, __ldg(&g_start[r0]), __ldg(&g_cnt[r0]), lane);
        float2 a = __ldg(&((const float2*)g_acc)[(size_t)r0 * 32 + lane]);
        va = make_float2(a.x + s.x, a.y + s.y);
    }
    {
        float2 s = row_gather(g_c2_h, __ldg(&g_start[r1]), __ldg(&g_cnt[r1]), lane);
        float2 a = __ldg(&((const float2*)g_acc)[(size_t)r1 * 32 + lane]);
        vb = make_float2(a.x + s.x, a.y + s.y);
    }

    float d = va.x * vb.x + va.y * vb.y;
    #pragma unroll
    for (int o = 16; o; o >>= 1) d += __shfl_xor_sync(FULL, d, o);
    if (lane == 0) out[w] = d * (1.0f / 16.0f);
}

extern "C" void kernel_launch(void* const* d_in, const int* in_sizes, int n_in,
                              void* d_out, int out_size) {
    const int*   users    = (const int*)  d_in[0];
    const int*   items    = (const int*)  d_in[1];
    const int*   adj_rows = (const int*)  d_in[2];
    const int*   adj_cols = (const int*)  d_in[3];
    const float* adj_vals = (const float*)d_in[4];
    const float* user_emb = (const float*)d_in[5];
    const float* item_emb = (const float*)d_in[6];
    float* out = (float*)d_out;

    const int nnz   = in_sizes[2];
    const int batch = in_sizes[0];

    const int T = 256;
    const int gb_elem = (N_NODES * DIM / 4 + T - 1) / T;
    const int gb_edge = (nnz + T - 1) / T;
    const int nb_scan = (N_NODES + 1023) / 1024;
    const int gb_row  = (N_NODES * 32 + T - 1) / T;
    const int gb_dot  = (batch * 32 + T - 1) / T;

    k_init_hist<<<gb_elem, T>>>(user_emb, item_emb);
    k_hist<<<gb_edge, T>>>(adj_rows, nnz);
    k_scan1<<<nb_scan, 1024>>>(N_NODES);
    k_scan23<<<nb_scan, 1024>>>(N_NODES, nb_scan);
    k_scatter<<<gb_edge, T>>>(adj_rows, adj_cols, adj_vals, nnz);

    k_gather<<<gb_row, T>>>(0, user_emb, item_emb);
    k_gather<<<gb_row, T>>>(1, user_emb, item_emb);

    k_dot<<<gb_dot, T>>>(users, items, out, batch);
}

// round 8
// speedup vs baseline: 1.2664x; 1.2664x over previous
#include <cuda_runtime.h>
#include <cuda_fp16.h>
#include <cstdint>

#define NUM_USERS 100000
#define NUM_ITEMS 50000
#define N_NODES   150000
#define DIM       64
#define NNZ_MAX   4800000
#define FULL      0xffffffffu

// ---- static device scratch (referenced ONLY from device code) ----
__device__ float   g_acc  [(size_t)N_NODES * DIM];      // fp32: ego + c1 + c2
__device__ __half2 g_ego_h[(size_t)N_NODES * DIM / 2];
__device__ __half2 g_c1_h [(size_t)N_NODES * DIM / 2];
__device__ __half2 g_c2_h [(size_t)N_NODES * DIM / 2];
__device__ int   g_cnt   [N_NODES];     // statically zero; re-zeroed by k_cleanup
__device__ int   g_start [N_NODES];
__device__ int   g_cursor[N_NODES];
__device__ int2  g_edges [NNZ_MAX];

// launch 1: fp16 ego convert + row histogram (g_cnt is pre-zeroed)
__global__ void k_init_hist(const float* __restrict__ ue, const float* __restrict__ ie,
                            const int* __restrict__ rows, int nnz) {
    int i = blockIdx.x * blockDim.x + threadIdx.x;
    if (i < N_NODES * DIM / 4) {
        const int u4 = NUM_USERS * DIM / 4;
        float4 v = (i < u4) ? ((const float4*)ue)[i] : ((const float4*)ie)[i - u4];
        g_ego_h[i * 2]     = __float22half2_rn(make_float2(v.x, v.y));
        g_ego_h[i * 2 + 1] = __float22half2_rn(make_float2(v.z, v.w));
    }
    if (i < nnz) atomicAdd(&g_cnt[__ldg(rows + i)], 1);
}

// launch 2: single-pass exclusive scan. Each block redundantly sums all
// preceding counts (≈44MB total reads chip-wide), then scans its own chunk.
__global__ void k_scan(int n) {
    __shared__ int sh[1024];
    __shared__ int s_prefix;
    int b = blockIdx.x, t = threadIdx.x;

    // 1) prefix = sum of cnt[0 .. b*1024)
    int acc = 0;
    int limit = b << 10;
    for (int i = t; i < limit; i += 1024) acc += g_cnt[i];
    sh[t] = acc;
    __syncthreads();
    #pragma unroll
    for (int off = 512; off; off >>= 1) {
        if (t < off) sh[t] += sh[t + off];
        __syncthreads();
    }
    if (t == 0) s_prefix = sh[0];
    __syncthreads();

    // 2) inclusive scan of own 1024 chunk -> exclusive global starts
    int i = (b << 10) + t;
    int v = (i < n) ? g_cnt[i] : 0;
    sh[t] = v;
    __syncthreads();
    #pragma unroll
    for (int off = 1; off < 1024; off <<= 1) {
        int u = (t >= off) ? sh[t - off] : 0;
        __syncthreads();
        sh[t] += u;
        __syncthreads();
    }
    if (i < n) {
        int s = sh[t] - v + s_prefix;
        g_start[i]  = s;
        g_cursor[i] = s;
    }
}

// launch 3: permute COO into row-grouped packed edges
__global__ void k_scatter(const int* __restrict__ rows, const int* __restrict__ cols,
                          const float* __restrict__ vals, int nnz) {
    int e = blockIdx.x * blockDim.x + threadIdx.x;
    if (e >= nnz) return;
    int r   = __ldg(rows + e);
    int pos = atomicAdd(&g_cursor[r], 1);
    g_edges[pos] = make_int2(__ldg(cols + e), __float_as_int(__ldg(vals + e)));
}

// warp-cooperative row gather (round-5 structure): lane-parallel edge loads,
// fully-unrolled immediate-lane shfl broadcast, half2 x-loads.
__device__ __forceinline__ float2 row_gather(const __half2* __restrict__ x,
                                             int base, int len, int lane) {
    const int2* __restrict__ ep = g_edges + base;
    float2 s = make_float2(0.f, 0.f);
    int nfull = len & ~31;
    for (int chunk = 0; chunk < nfull; chunk += 32) {
        int2 e = __ldg(ep + chunk + lane);
        #pragma unroll
        for (int k = 0; k < 32; k++) {
            int   col = __shfl_sync(FULL, e.x, k);
            float v   = __int_as_float(__shfl_sync(FULL, e.y, k));
            float2 xv = __half22float2(__ldg(&x[(size_t)col * 32 + lane]));
            s.x = fmaf(v, xv.x, s.x);
            s.y = fmaf(v, xv.y, s.y);
        }
    }
    int rem = len - nfull;
    if (rem) {
        int2 e = make_int2(0, 0);
        if (lane < rem) e = __ldg(ep + nfull + lane);
        for (int k = 0; k < rem; k++) {
            int   col = __shfl_sync(FULL, e.x, k);
            float v   = __int_as_float(__shfl_sync(FULL, e.y, k));
            float2 xv = __half22float2(__ldg(&x[(size_t)col * 32 + lane]));
            s.x = fmaf(v, xv.x, s.x);
            s.y = fmaf(v, xv.y, s.y);
        }
    }
    return s;
}

// launches 4,5: mode 0: c1 = A@ego_h ; acc = ego(fp32)+c1
//               mode 1: c2 = A@c1_h  ; acc += c2
__global__ void k_gather(int mode, const float* __restrict__ ue,
                         const float* __restrict__ ie) {
    int w = (blockIdx.x * blockDim.x + threadIdx.x) >> 5;
    if (w >= N_NODES) return;
    int lane = threadIdx.x & 31;

    const __half2* __restrict__ x = mode ? g_c1_h : g_ego_h;
    int base = __ldg(&g_start[w]);
    int len  = __ldg(&g_cnt[w]);

    float2 s = row_gather(x, base, len, lane);

    size_t o = (size_t)w * 32 + lane;
    float2 a;
    if (mode == 0) {
        g_c1_h[o] = __float22half2_rn(s);
        const float2* __restrict__ src = (w < NUM_USERS)
            ? (const float2*)ue + (size_t)w * 32
            : (const float2*)ie + (size_t)(w - NUM_USERS) * 32;
        a = __ldg(src + lane);
    } else {
        g_c2_h[o] = __float22half2_rn(s);
        a = ((float2*)g_acc)[o];
    }
    a.x += s.x; a.y += s.y;
    ((float2*)g_acc)[o] = a;
}

// launch 6: lazy layer 3 + dot, one warp per (user,item) pair
__global__ void k_dot(const int* __restrict__ users, const int* __restrict__ items,
                      float* __restrict__ out, int batch) {
    int w    = (blockIdx.x * blockDim.x + threadIdx.x) >> 5;
    int lane = threadIdx.x & 31;
    if (w >= batch) return;

    int r0 = __ldg(users + w);
    int r1 = NUM_USERS + __ldg(items + w);

    float2 va, vb;
    {
        float2 s = row_gather(g_c2_h, __ldg(&g_start[r0]), __ldg(&g_cnt[r0]), lane);
        float2 a = __ldg(&((const float2*)g_acc)[(size_t)r0 * 32 + lane]);
        va = make_float2(a.x + s.x, a.y + s.y);
    }
    {
        float2 s = row_gather(g_c2_h, __ldg(&g_start[r1]), __ldg(&g_cnt[r1]), lane);
        float2 a = __ldg(&((const float2*)g_acc)[(size_t)r1 * 32 + lane]);
        vb = make_float2(a.x + s.x, a.y + s.y);
    }

    float d = va.x * vb.x + va.y * vb.y;
    #pragma unroll
    for (int o = 16; o; o >>= 1) d += __shfl_xor_sync(FULL, d, o);
    if (lane == 0) out[w] = d * (1.0f / 16.0f);
}

// launch 7: reset g_cnt for the next replay (g_cnt no longer read this call)
__global__ void k_cleanup() {
    int i = blockIdx.x * blockDim.x + threadIdx.x;
    if (i < N_NODES / 4 + 1) {
        if (i * 4 + 3 < N_NODES) ((int4*)g_cnt)[i] = make_int4(0, 0, 0, 0);
        else for (int j = i * 4; j < N_NODES; j++) g_cnt[j] = 0;
    }
}

extern "C" void kernel_launch(void* const* d_in, const int* in_sizes, int n_in,
                              void* d_out, int out_size) {
    const int*   users    = (const int*)  d_in[0];
    const int*   items    = (const int*)  d_in[1];
    const int*   adj_rows = (const int*)  d_in[2];
    const int*   adj_cols = (const int*)  d_in[3];
    const float* adj_vals = (const float*)d_in[4];
    const float* user_emb = (const float*)d_in[5];
    const float* item_emb = (const float*)d_in[6];
    float* out = (float*)d_out;

    const int nnz   = in_sizes[2];
    const int batch = in_sizes[0];

    const int T = 256;
    const int work_init = (nnz > N_NODES * DIM / 4) ? nnz : N_NODES * DIM / 4;
    const int gb_init = (work_init + T - 1) / T;
    const int gb_edge = (nnz + T - 1) / T;
    const int nb_scan = (N_NODES + 1023) / 1024;
    const int gb_row  = (N_NODES * 32 + T - 1) / T;
    const int gb_dot  = (batch * 32 + T - 1) / T;
    const int gb_clr  = (N_NODES / 4 + 1 + T - 1) / T;

    k_init_hist<<<gb_init, T>>>(user_emb, item_emb, adj_rows, nnz);  // 1
    k_scan<<<nb_scan, 1024>>>(N_NODES);                              // 2
    k_scatter<<<gb_edge, T>>>(adj_rows, adj_cols, adj_vals, nnz);    // 3
    k_gather<<<gb_row, T>>>(0, user_emb, item_emb);                  // 4 <- profiled
    k_gather<<<gb_row, T>>>(1, user_emb, item_emb);                  // 5
    k_dot<<<gb_dot, T>>>(users, items, out, batch);                  // 6
    k_cleanup<<<gb_clr, T>>>();                                      // 7
}

// round 9
// speedup vs baseline: 1.5151x; 1.1964x over previous
#include <cuda_runtime.h>
#include <cuda_fp16.h>
#include <cstdint>

#define NUM_USERS 100000
#define NUM_ITEMS 50000
#define N_NODES   150000
#define DIM       64
#define NNZ_MAX   4800000
#define FULL      0xffffffffu

// ---- static device scratch (referenced ONLY from device code) ----
__device__ float   g_acc  [(size_t)N_NODES * DIM];      // fp32: ego + c1 + c2
__device__ __half2 g_ego_h[(size_t)N_NODES * DIM / 2];
__device__ __half2 g_c1_h [(size_t)N_NODES * DIM / 2];
__device__ __half2 g_c2_h [(size_t)N_NODES * DIM / 2];
__device__ int   g_cnt   [N_NODES];     // statically zero; re-zeroed by k_cleanup
__device__ int   g_start [N_NODES];
__device__ int   g_cursor[N_NODES];
__device__ int2  g_edges [NNZ_MAX];     // {col*32, val bits}, grouped by row

// launch 1: fp16 ego convert + row histogram (g_cnt pre-zeroed)
__global__ void k_init_hist(const float* __restrict__ ue, const float* __restrict__ ie,
                            const int* __restrict__ rows, int nnz) {
    int i = blockIdx.x * blockDim.x + threadIdx.x;
    if (i < N_NODES * DIM / 4) {
        const int u4 = NUM_USERS * DIM / 4;
        float4 v = (i < u4) ? ((const float4*)ue)[i] : ((const float4*)ie)[i - u4];
        g_ego_h[i * 2]     = __float22half2_rn(make_float2(v.x, v.y));
        g_ego_h[i * 2 + 1] = __float22half2_rn(make_float2(v.z, v.w));
    }
    if (i < nnz) atomicAdd(&g_cnt[__ldg(rows + i)], 1);
}

// launch 2: single-pass exclusive scan (redundant per-block prefix sums)
__global__ void k_scan(int n) {
    __shared__ int sh[1024];
    __shared__ int s_prefix;
    int b = blockIdx.x, t = threadIdx.x;

    int acc = 0;
    int limit = b << 10;
    for (int i = t; i < limit; i += 1024) acc += g_cnt[i];
    sh[t] = acc;
    __syncthreads();
    #pragma unroll
    for (int off = 512; off; off >>= 1) {
        if (t < off) sh[t] += sh[t + off];
        __syncthreads();
    }
    if (t == 0) s_prefix = sh[0];
    __syncthreads();

    int i = (b << 10) + t;
    int v = (i < n) ? g_cnt[i] : 0;
    sh[t] = v;
    __syncthreads();
    #pragma unroll
    for (int off = 1; off < 1024; off <<= 1) {
        int u = (t >= off) ? sh[t - off] : 0;
        __syncthreads();
        sh[t] += u;
        __syncthreads();
    }
    if (i < n) {
        int s = sh[t] - v + s_prefix;
        g_start[i]  = s;
        g_cursor[i] = s;
    }
}

// launch 3: permute COO into row-grouped packed edges; col pre-scaled by 32
__global__ void k_scatter(const int* __restrict__ rows, const int* __restrict__ cols,
                          const float* __restrict__ vals, int nnz) {
    int e = blockIdx.x * blockDim.x + threadIdx.x;
    if (e >= nnz) return;
    int r   = __ldg(rows + e);
    int pos = atomicAdd(&g_cursor[r], 1);
    g_edges[pos] = make_int2(__ldg(cols + e) * 32, __float_as_int(__ldg(vals + e)));
}

// launches 4,5: dual-row gather. One warp = 2 rows; half-warp = 1 row,
// 4 dims/lane. One width-16 SHFL broadcasts a different edge per half;
// one LDG.64 fetches x for two edges. Fixed 16-trip unrolled inner loop.
// mode 0: c1 = A@ego_h ; acc = ego(fp32)+c1
// mode 1: c2 = A@c1_h  ; acc += c2
__global__ void k_gather(int mode, const float* __restrict__ ue,
                         const float* __restrict__ ie) {
    int gw = (blockIdx.x * blockDim.x + threadIdx.x) >> 5;
    int r0 = gw * 2;
    if (r0 >= N_NODES) return;
    int lane = threadIdx.x & 31;
    int h    = lane >> 4;            // which row of the pair
    int sub  = lane & 15;            // dims 4*sub .. 4*sub+3
    int myrow = r0 + h;

    const __half2* __restrict__ x = mode ? g_c1_h : g_ego_h;
    const __half2* __restrict__ xl = x + 2 * sub;   // lane-fixed dim offset

    int base = __ldg(&g_start[myrow]);
    int len  = __ldg(&g_cnt[myrow]);
    int maxlen = max(len, __shfl_xor_sync(FULL, len, 16));
    const int2* __restrict__ ep = g_edges + base;

    float4 s = make_float4(0.f, 0.f, 0.f, 0.f);

    for (int chunk = 0; chunk < maxlen; chunk += 16) {
        int idx = chunk + sub;
        int2 e = make_int2(0, 0);                 // off 0, val +0.0f no-op
        if (idx < len) e = __ldg(ep + idx);
        #pragma unroll
        for (int k = 0; k < 16; k++) {
            int   off = __shfl_sync(FULL, e.x, k, 16);   // col*32, per-half
            float v   = __int_as_float(__shfl_sync(FULL, e.y, k, 16));
            uint2 raw = __ldg((const uint2*)(xl + off));
            __half2 h0 = *reinterpret_cast<__half2*>(&raw.x);
            __half2 h1 = *reinterpret_cast<__half2*>(&raw.y);
            float2 f0 = __half22float2(h0);
            float2 f1 = __half22float2(h1);
            s.x = fmaf(v, f0.x, s.x);
            s.y = fmaf(v, f0.y, s.y);
            s.z = fmaf(v, f1.x, s.z);
            s.w = fmaf(v, f1.y, s.w);
        }
    }

    // epilogue: each half-warp writes its own row (no cross-lane reduction)
    uint2 packed;
    __half2 o0 = __float22half2_rn(make_float2(s.x, s.y));
    __half2 o1 = __float22half2_rn(make_float2(s.z, s.w));
    packed.x = *reinterpret_cast<unsigned int*>(&o0);
    packed.y = *reinterpret_cast<unsigned int*>(&o1);
    size_t ho = (size_t)myrow * 32 + 2 * sub;
    if (mode == 0) *reinterpret_cast<uint2*>(&g_c1_h[ho]) = packed;
    else           *reinterpret_cast<uint2*>(&g_c2_h[ho]) = packed;

    float4 a;
    if (mode == 0) {
        const float4* __restrict__ src4 = (myrow < NUM_USERS)
            ? (const float4*)(ue + (size_t)myrow * DIM)
            : (const float4*)(ie + (size_t)(myrow - NUM_USERS) * DIM);
        a = __ldg(src4 + sub);
    } else {
        a = ((float4*)g_acc)[(size_t)myrow * 16 + sub];
    }
    a.x += s.x; a.y += s.y; a.z += s.z; a.w += s.w;
    ((float4*)g_acc)[(size_t)myrow * 16 + sub] = a;
}

// 32-lane row gather for lazy layer 3 (edges carry col*32)
__device__ __forceinline__ float2 row_gather(const __half2* __restrict__ x,
                                             int base, int len, int lane) {
    const int2* __restrict__ ep = g_edges + base;
    float2 s = make_float2(0.f, 0.f);
    for (int chunk = 0; chunk < len; chunk += 32) {
        int m = min(32, len - chunk);
        int2 e = make_int2(0, 0);
        if (lane < m) e = __ldg(ep + chunk + lane);
        #pragma unroll 8
        for (int k = 0; k < m; k++) {
            int   off = __shfl_sync(FULL, e.x, k);
            float v   = __int_as_float(__shfl_sync(FULL, e.y, k));
            float2 xv = __half22float2(__ldg(&x[(size_t)off + lane]));
            s.x = fmaf(v, xv.x, s.x);
            s.y = fmaf(v, xv.y, s.y);
        }
    }
    return s;
}

// launch 6: lazy layer 3 + dot, one warp per (user,item) pair
__global__ void k_dot(const int* __restrict__ users, const int* __restrict__ items,
                      float* __restrict__ out, int batch) {
    int w    = (blockIdx.x * blockDim.x + threadIdx.x) >> 5;
    int lane = threadIdx.x & 31;
    if (w >= batch) return;

    int r0 = __ldg(users + w);
    int r1 = NUM_USERS + __ldg(items + w);

    float2 va, vb;
    {
        float2 s = row_gather(g_c2_h, __ldg(&g_start[r0]), __ldg(&g_cnt[r0]), lane);
        float2 a = __ldg(&((const float2*)g_acc)[(size_t)r0 * 32 + lane]);
        va = make_float2(a.x + s.x, a.y + s.y);
    }
    {
        float2 s = row_gather(g_c2_h, __ldg(&g_start[r1]), __ldg(&g_cnt[r1]), lane);
        float2 a = __ldg(&((const float2*)g_acc)[(size_t)r1 * 32 + lane]);
        vb = make_float2(a.x + s.x, a.y + s.y);
    }

    float d = va.x * vb.x + va.y * vb.y;
    #pragma unroll
    for (int o = 16; o; o >>= 1) d += __shfl_xor_sync(FULL, d, o);
    if (lane == 0) out[w] = d * (1.0f / 16.0f);
}

// launch 7: reset g_cnt for the next replay
__global__ void k_cleanup() {
    int i = blockIdx.x * blockDim.x + threadIdx.x;
    if (i < N_NODES / 4 + 1) {
        if (i * 4 + 3 < N_NODES) ((int4*)g_cnt)[i] = make_int4(0, 0, 0, 0);
        else for (int j = i * 4; j < N_NODES; j++) g_cnt[j] = 0;
    }
}

extern "C" void kernel_launch(void* const* d_in, const int* in_sizes, int n_in,
                              void* d_out, int out_size) {
    const int*   users    = (const int*)  d_in[0];
    const int*   items    = (const int*)  d_in[1];
    const int*   adj_rows = (const int*)  d_in[2];
    const int*   adj_cols = (const int*)  d_in[3];
    const float* adj_vals = (const float*)d_in[4];
    const float* user_emb = (const float*)d_in[5];
    const float* item_emb = (const float*)d_in[6];
    float* out = (float*)d_out;

    const int nnz   = in_sizes[2];
    const int batch = in_sizes[0];

    const int T = 256;
    const int work_init = (nnz > N_NODES * DIM / 4) ? nnz : N_NODES * DIM / 4;
    const int gb_init = (work_init + T - 1) / T;
    const int gb_edge = (nnz + T - 1) / T;
    const int nb_scan = (N_NODES + 1023) / 1024;
    const int gb_row2 = ((N_NODES / 2) * 32 + T - 1) / T;
    const int gb_dot  = (batch * 32 + T - 1) / T;
    const int gb_clr  = (N_NODES / 4 + 1 + T - 1) / T;

    k_init_hist<<<gb_init, T>>>(user_emb, item_emb, adj_rows, nnz);  // 1
    k_scan<<<nb_scan, 1024>>>(N_NODES);                              // 2
    k_scatter<<<gb_edge, T>>>(adj_rows, adj_cols, adj_vals, nnz);    // 3
    k_gather<<<gb_row2, T>>>(0, user_emb, item_emb);                 // 4 <- profiled
    k_gather<<<gb_row2, T>>>(1, user_emb, item_emb);                 // 5
    k_dot<<<gb_dot, T>>>(users, items, out, batch);                  // 6
    k_cleanup<<<gb_clr, T>>>();                                      // 7
}